// round 17
// baseline (speedup 1.0000x reference)
#include <cuda_runtime.h>

#define NB    2048
#define NPAIR (NB / 2)
#define GGRID 592     // 148 SMs x 4 CTAs: persistent work-steal grid
#define KD    256
#define PD    256
#define SD    10
#define PADS  12
#define LAMB  0.5f
#define EPSF  1e-9f
#define NEG_PAD -1e30f
#define SELT  320     // sel kernel threads: 10 warps, one slice each

__device__ float    g_cmag[NB * SD * PD];   // masked |X@P| scratch (20 MB)
__device__ float    g_logmse[NB];
__device__ float    g_pen[NB];
__device__ unsigned g_done = 0;
__device__ unsigned g_work = 0;             // gemm work-steal counter

typedef unsigned long long ull;

__device__ __forceinline__ ull ffma2(ull a, ull b, ull c) {
    ull d;
    asm("fma.rn.f32x2 %0, %1, %2, %3;" : "=l"(d) : "l"(a), "l"(b), "l"(c));
    return d;
}
__device__ __forceinline__ ull pack2(float x) {
    unsigned u = __float_as_uint(x);
    ull d;
    asm("mov.b64 %0, {%1, %2};" : "=l"(d) : "r"(u), "r"(u));
    return d;
}
__device__ __forceinline__ void unpack2(ull a, float& lo, float& hi) {
    unsigned l, h;
    asm("mov.b64 {%0, %1}, %2;" : "=r"(l), "=r"(h) : "l"(a));
    lo = __uint_as_float(l);
    hi = __uint_as_float(h);
}
__device__ __forceinline__ float4 ldcs4(const float* p) {
    float4 v;
    asm volatile("ld.global.cs.v4.f32 {%0,%1,%2,%3}, [%4];"
                 : "=f"(v.x), "=f"(v.y), "=f"(v.z), "=f"(v.w) : "l"(p));
    return v;
}

// ======================= kernel 1: persistent streaming GEMM =======================
// 592 CTAs of 128 threads; each CTA steals batch-pairs. Per pair: 2 batches x 64
// threads, each thread owns 4 adjacent columns (LDG.128), 16 rows of P in flight.
__global__ __launch_bounds__(128, 4)
void vil_gemm_kernel(const float* __restrict__ Pmat,
                     const float* __restrict__ params,
                     const float* __restrict__ Xs)
{
    __shared__ __align__(16) float xst[2][KD * PADS];   // 24 KB
    __shared__ unsigned s_pair;

    const int tid  = threadIdx.x;
    const int half = tid >> 6;
    const int ltid = tid & 63;

    for (;;) {
        if (tid == 0) s_pair = atomicAdd(&g_work, 1u);
        __syncthreads();                 // prev iter done + s_pair visible
        const unsigned pair = s_pair;
        if (pair >= NPAIR) break;        // uniform exit

        const int b = ((int)pair << 1) | half;

        int n = (int)params[b * 3 + 0];
        int k = (int)params[b * 3 + 1];
        if (k > KD) k = KD;
        int pv = n - k;
        if (pv < 0) pv = 0;
        if (pv > PD) pv = PD;

        // ---- stage X transposed + masked into smem (float4 loads) ----
        const float4* Xb4 = reinterpret_cast<const float4*>(Xs + (size_t)b * SD * KD);
        float* xh = xst[half];
        for (int i = ltid; i < SD * (KD / 4); i += 64) {
            int s  = i >> 6;             // KD/4 = 64
            int j  = i & 63;
            int kk = j << 2;
            float4 v = Xb4[i];
            xh[(kk + 0) * PADS + s] = (kk + 0 < k) ? v.x : 0.0f;
            xh[(kk + 1) * PADS + s] = (kk + 1 < k) ? v.y : 0.0f;
            xh[(kk + 2) * PADS + s] = (kk + 2 < k) ? v.z : 0.0f;
            xh[(kk + 3) * PADS + s] = (kk + 3 < k) ? v.w : 0.0f;
        }
        __syncthreads();                 // xst ready

        // ---- GEMM: 4 adjacent columns per thread (LDG.128); pv-guarded ----
        const int c0 = ltid << 2;
        const float* Pb = Pmat + (size_t)b * KD * PD + c0;

        ull acc0[5] = {0,0,0,0,0};
        ull acc1[5] = {0,0,0,0,0};
        ull acc2[5] = {0,0,0,0,0};
        ull acc3[5] = {0,0,0,0,0};

        if (c0 < pv) {
            float4 bufA[8], bufB[8];
#pragma unroll
            for (int u = 0; u < 8; ++u) bufA[u] = ldcs4(Pb + u * PD);
#pragma unroll
            for (int u = 0; u < 8; ++u) bufB[u] = ldcs4(Pb + (8 + u) * PD);

            for (int kk0 = 0; kk0 < KD; kk0 += 16) {
                const bool moreA = (kk0 + 16) < KD;
#pragma unroll
                for (int u = 0; u < 8; ++u) {
                    const float4 pcur = bufA[u];
                    if (moreA) bufA[u] = ldcs4(Pb + (kk0 + 16 + u) * PD);
                    const float* row = xh + (kk0 + u) * PADS;
                    ulonglong2 q0 = *reinterpret_cast<const ulonglong2*>(row);
                    ulonglong2 q1 = *reinterpret_cast<const ulonglong2*>(row + 4);
                    ull x89       = *reinterpret_cast<const ull*>(row + 8);
                    ull p0 = pack2(pcur.x), p1 = pack2(pcur.y);
                    ull p2 = pack2(pcur.z), p3 = pack2(pcur.w);
                    acc0[0] = ffma2(q0.x, p0, acc0[0]);  acc1[0] = ffma2(q0.x, p1, acc1[0]);
                    acc2[0] = ffma2(q0.x, p2, acc2[0]);  acc3[0] = ffma2(q0.x, p3, acc3[0]);
                    acc0[1] = ffma2(q0.y, p0, acc0[1]);  acc1[1] = ffma2(q0.y, p1, acc1[1]);
                    acc2[1] = ffma2(q0.y, p2, acc2[1]);  acc3[1] = ffma2(q0.y, p3, acc3[1]);
                    acc0[2] = ffma2(q1.x, p0, acc0[2]);  acc1[2] = ffma2(q1.x, p1, acc1[2]);
                    acc2[2] = ffma2(q1.x, p2, acc2[2]);  acc3[2] = ffma2(q1.x, p3, acc3[2]);
                    acc0[3] = ffma2(q1.y, p0, acc0[3]);  acc1[3] = ffma2(q1.y, p1, acc1[3]);
                    acc2[3] = ffma2(q1.y, p2, acc2[3]);  acc3[3] = ffma2(q1.y, p3, acc3[3]);
                    acc0[4] = ffma2(x89,  p0, acc0[4]);  acc1[4] = ffma2(x89,  p1, acc1[4]);
                    acc2[4] = ffma2(x89,  p2, acc2[4]);  acc3[4] = ffma2(x89,  p3, acc3[4]);
                }
                const bool moreB = (kk0 + 24) < KD;
#pragma unroll
                for (int u = 0; u < 8; ++u) {
                    const float4 pcur = bufB[u];
                    if (moreB) bufB[u] = ldcs4(Pb + (kk0 + 24 + u) * PD);
                    const float* row = xh + (kk0 + 8 + u) * PADS;
                    ulonglong2 q0 = *reinterpret_cast<const ulonglong2*>(row);
                    ulonglong2 q1 = *reinterpret_cast<const ulonglong2*>(row + 4);
                    ull x89       = *reinterpret_cast<const ull*>(row + 8);
                    ull p0 = pack2(pcur.x), p1 = pack2(pcur.y);
                    ull p2 = pack2(pcur.z), p3 = pack2(pcur.w);
                    acc0[0] = ffma2(q0.x, p0, acc0[0]);  acc1[0] = ffma2(q0.x, p1, acc1[0]);
                    acc2[0] = ffma2(q0.x, p2, acc2[0]);  acc3[0] = ffma2(q0.x, p3, acc3[0]);
                    acc0[1] = ffma2(q0.y, p0, acc0[1]);  acc1[1] = ffma2(q0.y, p1, acc1[1]);
                    acc2[1] = ffma2(q0.y, p2, acc2[1]);  acc3[1] = ffma2(q0.y, p3, acc3[1]);
                    acc0[2] = ffma2(q1.x, p0, acc0[2]);  acc1[2] = ffma2(q1.x, p1, acc1[2]);
                    acc2[2] = ffma2(q1.x, p2, acc2[2]);  acc3[2] = ffma2(q1.x, p3, acc3[2]);
                    acc0[3] = ffma2(q1.y, p0, acc0[3]);  acc1[3] = ffma2(q1.y, p1, acc1[3]);
                    acc2[3] = ffma2(q1.y, p2, acc2[3]);  acc3[3] = ffma2(q1.y, p3, acc3[3]);
                    acc0[4] = ffma2(x89,  p0, acc0[4]);  acc1[4] = ffma2(x89,  p1, acc1[4]);
                    acc2[4] = ffma2(x89,  p2, acc2[4]);  acc3[4] = ffma2(x89,  p3, acc3[4]);
                }
            }
        }

        // ---- write masked |C| for 4 columns (STG.128 per s) ----
        {
            const bool ok0 = (c0 + 0) < pv;
            const bool ok1 = (c0 + 1) < pv;
            const bool ok2 = (c0 + 2) < pv;
            const bool ok3 = (c0 + 3) < pv;
            float* dst = g_cmag + (size_t)b * SD * PD + c0;
#pragma unroll
            for (int j = 0; j < 5; ++j) {
                float v0l, v0h, v1l, v1h, v2l, v2h, v3l, v3h;
                unpack2(acc0[j], v0l, v0h);
                unpack2(acc1[j], v1l, v1h);
                unpack2(acc2[j], v2l, v2h);
                unpack2(acc3[j], v3l, v3h);
                float4 wlo, whi;
                wlo.x = ok0 ? fabsf(v0l) : -1.0f;
                wlo.y = ok1 ? fabsf(v1l) : -1.0f;
                wlo.z = ok2 ? fabsf(v2l) : -1.0f;
                wlo.w = ok3 ? fabsf(v3l) : -1.0f;
                whi.x = ok0 ? fabsf(v0h) : -1.0f;
                whi.y = ok1 ? fabsf(v1h) : -1.0f;
                whi.z = ok2 ? fabsf(v2h) : -1.0f;
                whi.w = ok3 ? fabsf(v3h) : -1.0f;
                *reinterpret_cast<float4*>(dst + (2 * j)     * PD) = wlo;
                *reinterpret_cast<float4*>(dst + (2 * j + 1) * PD) = whi;
            }
        }
    }
}

// ============== kernel 2: selection + losses + final reduction ==============
template<int R>
__device__ __forceinline__ float slice_hm(const float* __restrict__ xr,
                                          const float* __restrict__ cr,
                                          int k, int lane)
{
    float cand[16];
#pragma unroll
    for (int j = 0; j < 8; ++j) {
        int kk = lane + 32 * j;
        float v = xr[kk];
        cand[j] = (kk < k) ? fabsf(v) : -1.0f;
    }
#pragma unroll
    for (int j = 0; j < 8; ++j)
        cand[8 + j] = cr[lane + 32 * j];     // cols >= pv already hold -1

    float t[R];
#pragma unroll
    for (int i = 0; i < R; ++i) t[i] = NEG_PAD;
#pragma unroll
    for (int j = 0; j < 16; ++j) {
        float v = cand[j];
#pragma unroll
        for (int i = R - 1; i >= 1; --i) t[i] = fmaxf(t[i], fminf(t[i - 1], v));
        t[0] = fmaxf(t[0], v);
    }

#pragma unroll
    for (int st = 0; st < 5; ++st) {
        float r[R], o[R];
#pragma unroll
        for (int i = 0; i < R; ++i)
            r[i] = __shfl_xor_sync(0xffffffffu, t[i], 1 << st);
#pragma unroll
        for (int j = 0; j < R; ++j) {
            float mx = fmaxf(t[j], r[j]);
#pragma unroll
            for (int i = 0; i < j; ++i)
                mx = fmaxf(mx, fminf(t[i], r[j - 1 - i]));
            o[j] = mx;
        }
#pragma unroll
        for (int i = 0; i < R; ++i) t[i] = o[i];
    }
    return t[0] / (t[R - 1] + EPSF);
}

__global__ __launch_bounds__(SELT)
void vil_sel_kernel(const float* __restrict__ y_pred,
                    const float* __restrict__ y_true,
                    const float* __restrict__ params,
                    const float* __restrict__ Xs,
                    float* __restrict__ out,
                    int out_size)
{
    __shared__ float warr[SD];
    __shared__ float sm1[SD + 6], sm2[SD + 6];
    __shared__ unsigned is_last;

    const int b    = blockIdx.x;
    const int tid  = threadIdx.x;
    const int lane = tid & 31;
    const int wl   = tid >> 5;          // 0..9 — one slice per warp

    // reset the gemm work-steal counter for the next graph replay
    if (b == 0 && tid == 0) g_work = 0;

    int n = (int)params[b * 3 + 0];
    int k = (int)params[b * 3 + 1];
    int m = (int)params[b * 3 + 2];
    if (k > KD) k = KD;
    if (m < 0) m = 0;
    if (m > 8) m = 8;

    const float* xr = Xs     + (size_t)b * SD * KD + wl * KD;
    const float* cr = g_cmag + (size_t)b * SD * PD + wl * PD;

    float s_hm;
    switch (m) {
        case 0: s_hm = slice_hm<1>(xr, cr, k, lane); break;
        case 1: s_hm = slice_hm<2>(xr, cr, k, lane); break;
        case 2: s_hm = slice_hm<3>(xr, cr, k, lane); break;
        case 3: s_hm = slice_hm<4>(xr, cr, k, lane); break;
        case 4: s_hm = slice_hm<5>(xr, cr, k, lane); break;
        case 5: s_hm = slice_hm<6>(xr, cr, k, lane); break;
        case 6: s_hm = slice_hm<7>(xr, cr, k, lane); break;
        case 7: s_hm = slice_hm<8>(xr, cr, k, lane); break;
        default: s_hm = slice_hm<9>(xr, cr, k, lane); break;
    }
    if (lane == 0) warr[wl] = s_hm;
    __syncthreads();

    if (tid == 0) {
        float mh = warr[0];
#pragma unroll
        for (int w = 1; w < SD; ++w) mh = fmaxf(mh, warr[w]);
        float yp = y_pred[b];
        float lt = log2f(fmaxf(y_true[b], EPSF));
        float lp = log2f(fmaxf(yp, EPSF));
        float d  = lt - lp;
        g_logmse[b] = d * d;
        bool valid  = (m + 1) <= n;
        g_pen[b]    = valid ? fmaxf(mh - yp, 0.0f) : 0.0f;
        __threadfence();
        unsigned prev = atomicAdd(&g_done, 1u);
        is_last = (prev == NB - 1) ? 1u : 0u;
    }
    __syncthreads();

    // ---- last block performs the deterministic final reduction ----
    if (is_last) {
        __threadfence();
        float s1 = 0.0f, s2 = 0.0f;
        for (int i = tid; i < NB; i += SELT) {   // fixed order -> deterministic
            s1 += g_logmse[i];
            s2 += g_pen[i];
        }
#pragma unroll
        for (int off = 16; off; off >>= 1) {     // fixed shfl tree -> deterministic
            s1 += __shfl_down_sync(0xffffffffu, s1, off);
            s2 += __shfl_down_sync(0xffffffffu, s2, off);
        }
        if (lane == 0) { sm1[wl] = s1; sm2[wl] = s2; }
        __syncthreads();
        if (tid == 0) {
            float t1 = 0.0f, t2 = 0.0f;
#pragma unroll
            for (int w = 0; w < SD; ++w) { t1 += sm1[w]; t2 += sm2[w]; }
            float logmse = t1 / (float)NB;
            float viol   = t2 / (float)NB;
            out[0] = logmse + LAMB * viol;
            if (out_size > 1) out[1] = logmse;
            if (out_size > 2) out[2] = viol;
            g_done = 0;   // reset for next graph replay
        }
    }
}

extern "C" void kernel_launch(void* const* d_in, const int* in_sizes, int n_in,
                              void* d_out, int out_size)
{
    const float* y_pred = (const float*)d_in[0];
    const float* y_true = (const float*)d_in[1];
    const float* Pmat   = (const float*)d_in[2];
    const float* params = (const float*)d_in[3];
    const float* Xs     = (const float*)d_in[4];

    vil_gemm_kernel<<<GGRID, 128>>>(Pmat, params, Xs);
    vil_sel_kernel<<<NB, SELT>>>(y_pred, y_true, params, Xs,
                                 (float*)d_out, out_size);
}